// round 5
// baseline (speedup 1.0000x reference)
#include <cuda_runtime.h>

// AffineTransformation: B=32, H=W=512, C=1, fp32.
// d_in[0] = theta [32,6] f32, d_in[1] = image [32,512,512,1] f32 -> out same shape.
//
// Pixel-space derivatives (exact): d(fx)/d(col)=t0, d(fx)/d(row)=t1,
//                                  d(fy)/d(col)=t3, d(fy)/d(row)=t4.
// Gather cost is driven by how many image ROWS a warp's 32 addresses span.
// Per batch we map warp lanes along the screen axis with smaller |d(fy)|:
//   mapping A (lanes->cols) if |t3| <= |t4|, else mapping B (lanes->rows).
// Mapping B stores via a padded smem transpose so stores stay coalesced.

#define BB 32
#define HH 512
#define WW 512

__global__ __launch_bounds__(256, 6)
void affine_sample_kernel(const float* __restrict__ theta,
                          const float* __restrict__ image,
                          float* __restrict__ out)
{
    __shared__ float tile[32][33];   // [local_row][local_col], padded

    const int b = blockIdx.z;

    const float t0 = __ldg(theta + b * 6 + 0);
    const float t1 = __ldg(theta + b * 6 + 1);
    const float t2 = __ldg(theta + b * 6 + 2);
    const float t3 = __ldg(theta + b * 6 + 3);
    const float t4 = __ldg(theta + b * 6 + 4);
    const float t5 = __ldg(theta + b * 6 + 5);

    const int tx = threadIdx.x;          // 0..31  (lane)
    const int ty = threadIdx.y;          // 0..7
    const int col0 = blockIdx.x * 32;
    const int row0 = blockIdx.y * 32;

    const bool mapB = fabsf(t4) < fabsf(t3);   // uniform per block

    // This thread's first pixel + per-j pixel step direction
    const int pcol = mapB ? (col0 + ty * 4) : (col0 + tx);
    const int prow = mapB ? (row0 + tx)     : (row0 + ty * 4);
    const float djx = mapB ? t0 : t1;    // d(fx) per j-step
    const float djy = mapB ? t3 : t4;    // d(fy) per j-step

    const float inv_w = 2.0f / (float)(WW - 1);
    const float inv_h = 2.0f / (float)(HH - 1);
    const float xn = -1.0f + (float)pcol * inv_w;
    const float yn = -1.0f + (float)prow * inv_h;

    const float fx0 = 0.5f * (float)(WW - 1) * (t0 * xn + t1 * yn + t2) + 0.5f * (float)(WW - 1);
    const float fy0 = 0.5f * (float)(HH - 1) * (t3 * xn + t4 * yn + t5) + 0.5f * (float)(HH - 1);
    const float fx3 = fmaf(3.0f, djx, fx0);
    const float fy3 = fmaf(3.0f, djy, fy0);

    const float lox = fminf(fx0, fx3), hix = fmaxf(fx0, fx3);
    const float loy = fminf(fy0, fy3), hiy = fmaxf(fy0, fy3);

    const float* __restrict__ img = image + b * (HH * WW);

    float r[4];

    if (hix <= -1.0f || lox >= (float)WW || hiy <= -1.0f || loy >= (float)HH) {
        // zero coverage for all 4 px
        r[0] = r[1] = r[2] = r[3] = 0.0f;
    } else if (lox >= 0.0f && hix < (float)(WW - 1) && loy >= 0.0f && hiy < (float)(HH - 1)) {
        // fully interior: no clamps, trunc == floor, plain bilinear lerp.
        float ax[4], ay[4];
        int   base[4];
        #pragma unroll
        for (int j = 0; j < 4; j++) {
            const float fx = fmaf((float)j, djx, fx0);
            const float fy = fmaf((float)j, djy, fy0);
            const int ix = (int)fx;
            const int iy = (int)fy;
            ax[j] = fx - (float)ix;
            ay[j] = fy - (float)iy;
            base[j] = iy * WW + ix;
        }
        float va[4], vb[4], vc[4], vd[4];
        #pragma unroll
        for (int j = 0; j < 4; j++) {
            va[j] = __ldg(img + base[j]);
            vb[j] = __ldg(img + base[j] + 1);
            vc[j] = __ldg(img + base[j] + WW);
            vd[j] = __ldg(img + base[j] + WW + 1);
        }
        #pragma unroll
        for (int j = 0; j < 4; j++) {
            const float h0 = fmaf(ax[j], vb[j] - va[j], va[j]);
            const float h1 = fmaf(ax[j], vd[j] - vc[j], vc[j]);
            r[j] = __saturatef(fmaf(ay[j], h1 - h0, h0));
        }
    } else {
        // border: full reference semantics (clip-then-delta, edge double-count)
        #pragma unroll
        for (int j = 0; j < 4; j++) {
            const float fx = fmaf((float)j, djx, fx0);
            const float fy = fmaf((float)j, djy, fy0);

            const float flx = floorf(fx);
            const float fly = floorf(fy);

            const float x0 = fminf(fmaxf(flx,        0.0f), (float)(WW - 1));
            const float x1 = fminf(fmaxf(flx + 1.0f, 0.0f), (float)(WW - 1));
            const float y0 = fminf(fmaxf(fly,        0.0f), (float)(HH - 1));
            const float y1 = fminf(fmaxf(fly + 1.0f, 0.0f), (float)(HH - 1));

            const float wx0 = fmaxf(0.0f, 1.0f - fabsf(fx - x0));
            const float wx1 = fmaxf(0.0f, 1.0f - fabsf(fx - x1));
            const float wy0 = fmaxf(0.0f, 1.0f - fabsf(fy - y0));
            const float wy1 = fmaxf(0.0f, 1.0f - fabsf(fy - y1));

            float v = 0.0f;
            if ((wx0 + wx1) > 0.0f && (wy0 + wy1) > 0.0f) {
                const int ix0 = (int)x0;
                const int ix1 = (int)x1;
                const int r0o = (int)y0 * WW;
                const int r1o = (int)y1 * WW;
                v = wy0 * (wx0 * __ldg(img + r0o + ix0) + wx1 * __ldg(img + r0o + ix1))
                  + wy1 * (wx0 * __ldg(img + r1o + ix0) + wx1 * __ldg(img + r1o + ix1));
            }
            r[j] = __saturatef(v);
        }
    }

    const int obase = (b * HH + row0 + ty * 4) * WW + col0 + tx;  // int32 safe

    if (!mapB) {
        // pixels already laid out for coalesced stores
        #pragma unroll
        for (int j = 0; j < 4; j++) out[obase + j * WW] = r[j];
    } else {
        // pixel (row0+tx, col0+ty*4+j) -> smem transpose -> coalesced store
        #pragma unroll
        for (int j = 0; j < 4; j++) tile[tx][ty * 4 + j] = r[j];
        __syncthreads();
        #pragma unroll
        for (int j = 0; j < 4; j++) out[obase + j * WW] = tile[ty * 4 + j][tx];
    }
}

extern "C" void kernel_launch(void* const* d_in, const int* in_sizes, int n_in,
                              void* d_out, int out_size)
{
    const float* theta = (const float*)d_in[0];
    const float* image = (const float*)d_in[1];
    float* out = (float*)d_out;

    dim3 block(32, 8, 1);                  // 256 threads; tile = 32x32 px
    dim3 grid(WW / 32, HH / 32, BB);       // (16, 16, 32) = 8192 blocks
    affine_sample_kernel<<<grid, block>>>(theta, image, out);
}